// round 3
// baseline (speedup 1.0000x reference)
#include <cuda_runtime.h>
#include <cstdint>

#define B_  8
#define F_  512
#define K_  8
#define N_  2048
#define FKN (F_*K_*N_)   // per-batch element stride = 8388608
#define KN  (K_*N_)      // per-channel stride = 16384

typedef unsigned long long u64;

__device__ __forceinline__ u64 pack2(float a) {
    u64 r;
    asm("mov.b64 %0, {%1, %1};" : "=l"(r) : "f"(a));
    return r;
}
__device__ __forceinline__ void fma2(u64& d, u64 a, u64 b) {
    asm("fma.rn.f32x2 %0, %1, %2, %0;" : "+l"(d) : "l"(a), "l"(b));
}
__device__ __forceinline__ float2 unpack2(u64 v) {
    float lo, hi;
    asm("mov.b64 {%0, %1}, %2;" : "=f"(lo), "=f"(hi) : "l"(v));
    return make_float2(lo, hi);
}

// Fused kernel:
//   d[b,g,k,n] = sum_f W[g,f] * x[b,f,k,n]
//   kf[b,g,n]  = x[b,g,:,n]^T G d[b,g,:,n]   (G = Killing Gram, sparse, hardcoded)
//   out        = (kf<=0) ? x : x + kf*d
//
// CTA: b = blockIdx.z, g-rows [g0, g0+64), n-cols [n0, n0+32), all 8 k.
// 256 threads: lane = n index (0..31), wrow = t>>5 (0..7).
// Thread owns 8 g-rows (g0 + r*8 + wrow) x 8 k x 1 n => 32 f32x2 accumulators.
__global__ void __launch_bounds__(256, 2)
lnkr_fused_kernel(const float* __restrict__ x,
                  const float* __restrict__ W,
                  float* __restrict__ out)
{
    __shared__ float Ws[16][64];      // Ws[f_local][g_local]  (W transposed)
    __shared__ float Xs[16][32][10];  // Xs[f_local][n_local][k], padded 8->10

    const int t    = threadIdx.x;
    const int lane = t & 31;   // n within tile
    const int wrow = t >> 5;   // 0..7: k for loads, g sub-row for compute
    const int b    = blockIdx.z;
    const int g0   = blockIdx.y * 64;
    const int n0   = blockIdx.x * 32;

    // Global load pointers
    // W tile: thread loads float4 of row (g0 + t>>2), cols f0 + (t&3)*4 .. +3
    const float* wg = W + (size_t)(g0 + (t >> 2)) * F_ + ((t & 3) << 2);
    // X tile: thread loads 16 scalars: channels f0..f0+15 at fixed (k=wrow, n=n0+lane)
    const float* xg = x + (size_t)b * FKN + (size_t)wrow * N_ + n0 + lane;

    u64 acc[8][4];
#pragma unroll
    for (int r = 0; r < 8; ++r)
#pragma unroll
        for (int kp = 0; kp < 4; ++kp) acc[r][kp] = 0ull;

    float4 wreg;
    float  xreg[16];

    // Prefetch + store tile 0
    wreg = *(const float4*)(wg);
#pragma unroll
    for (int j = 0; j < 16; ++j) xreg[j] = xg[(size_t)j * KN];
    {
        const int fl0 = (t & 3) * 4, gl = t >> 2;
        Ws[fl0 + 0][gl] = wreg.x; Ws[fl0 + 1][gl] = wreg.y;
        Ws[fl0 + 2][gl] = wreg.z; Ws[fl0 + 3][gl] = wreg.w;
#pragma unroll
        for (int j = 0; j < 16; ++j) Xs[j][lane][wrow] = xreg[j];
    }
    __syncthreads();

    for (int tile = 0; tile < 32; ++tile) {
        // Prefetch next tile into registers (latency hidden under compute)
        if (tile < 31) {
            const int f0 = (tile + 1) * 16;
            wreg = *(const float4*)(wg + f0);
#pragma unroll
            for (int j = 0; j < 16; ++j) xreg[j] = xg[(size_t)(f0 + j) * KN];
        }

        // Compute on current smem tile
#pragma unroll
        for (int fl = 0; fl < 16; ++fl) {
            u64 wp[8];
#pragma unroll
            for (int r = 0; r < 8; ++r)
                wp[r] = pack2(Ws[fl][r * 8 + wrow]);   // lane-uniform -> broadcast LDS

            u64 xv[4];
            const u64* xp = (const u64*)(&Xs[fl][lane][0]);  // 8B-aligned (10 floats/row)
#pragma unroll
            for (int kp = 0; kp < 4; ++kp) xv[kp] = xp[kp];

#pragma unroll
            for (int r = 0; r < 8; ++r)
#pragma unroll
                for (int kp = 0; kp < 4; ++kp)
                    fma2(acc[r][kp], xv[kp], wp[r]);
        }
        __syncthreads();

        if (tile < 31) {
            const int fl0 = (t & 3) * 4, gl = t >> 2;
            Ws[fl0 + 0][gl] = wreg.x; Ws[fl0 + 1][gl] = wreg.y;
            Ws[fl0 + 2][gl] = wreg.z; Ws[fl0 + 3][gl] = wreg.w;
#pragma unroll
            for (int j = 0; j < 16; ++j) Xs[j][lane][wrow] = xreg[j];
            __syncthreads();
        }
    }

    // Epilogue: per owned g-row, reload x vector over k, Killing form, gated update.
#pragma unroll
    for (int r = 0; r < 8; ++r) {
        const int g = g0 + r * 8 + wrow;
        const size_t base = (size_t)b * FKN + (size_t)g * KN + n0 + lane;

        float xs[8];
#pragma unroll
        for (int k = 0; k < 8; ++k) xs[k] = x[base + (size_t)k * N_];

        float d[8];
#pragma unroll
        for (int kp = 0; kp < 4; ++kp) {
            float2 v = unpack2(acc[r][kp]);
            d[2 * kp] = v.x; d[2 * kp + 1] = v.y;
        }

        // kf = x^T G d with G_ab = 6 tr(E_a E_b) (sl(3) Chevalley basis):
        // nonzeros: G00=G44=12, G04=G40=-6, G13=G31=G26=G62=G57=G75=6
        const float kf = 6.0f * (2.0f * xs[0] * d[0] + 2.0f * xs[4] * d[4]
                                 - xs[0] * d[4] - xs[4] * d[0]
                                 + xs[1] * d[3] + xs[3] * d[1]
                                 + xs[2] * d[6] + xs[6] * d[2]
                                 + xs[5] * d[7] + xs[7] * d[5]);

#pragma unroll
        for (int k = 0; k < 8; ++k)
            out[base + (size_t)k * N_] = (kf <= 0.0f) ? xs[k] : fmaf(kf, d[k], xs[k]);
    }
}

extern "C" void kernel_launch(void* const* d_in, const int* in_sizes, int n_in,
                              void* d_out, int out_size)
{
    const float* a0 = (const float*)d_in[0];
    const float* a1 = (const float*)d_in[1];
    // x is the large tensor (B*F*K*N), W is F*F — pick by size for safety.
    const float* x = a0; const float* W = a1;
    if (n_in >= 2 && in_sizes[0] < in_sizes[1]) { x = a1; W = a0; }

    dim3 grid(N_ / 32, F_ / 64, B_);   // (64, 8, 8)
    lnkr_fused_kernel<<<grid, 256>>>(x, W, (float*)d_out);
}

// round 5
// speedup vs baseline: 1.7892x; 1.7892x over previous
#include <cuda_runtime.h>
#include <cuda_bf16.h>
#include <cstdint>

#define F_   512
#define KN_  16384       // k*n per (b,f)
#define FKN  8388608     // F_*KN_

// -------- device scratch (allocs forbidden) --------
__device__ __nv_bfloat16 g_W_hi[512 * 512];
__device__ __nv_bfloat16 g_W_lo[512 * 512];

// -------- prep: split W into bf16 hi/lo --------
__global__ void prep_w(const float* __restrict__ W) {
    int i = blockIdx.x * 512 + threadIdx.x;
    float v = W[i];
    __nv_bfloat16 h = __float2bfloat16(v);
    g_W_hi[i] = h;
    g_W_lo[i] = __float2bfloat16(v - __bfloat162float(h));
}

// legacy tensor-core mma (baseline PTX, works on plain sm_103 target)
static __device__ __forceinline__ void mma16816(float* c,
        uint32_t a0, uint32_t a1, uint32_t a2, uint32_t a3,
        uint32_t b0, uint32_t b1) {
    asm volatile(
        "mma.sync.aligned.m16n8k16.row.col.f32.bf16.bf16.f32 "
        "{%0,%1,%2,%3}, {%4,%5,%6,%7}, {%8,%9}, {%0,%1,%2,%3};"
        : "+f"(c[0]), "+f"(c[1]), "+f"(c[2]), "+f"(c[3])
        : "r"(a0), "r"(a1), "r"(a2), "r"(a3), "r"(b0), "r"(b1));
}

// ---------------- fused kernel ----------------
// CTA: g range 128 (gc), token tile = all 8 k x 32 n (b, ntile). 512 threads.
// smem (dynamic, 69632 B):
//   K-loop:  stage s in {0,1}:
//     XH[s] at s*20480        : 256 tau x 16 f bf16, row stride 40 B
//     XL[s] at s*20480+10240
//     WH[s] at 40960+s*8192   : 128 g x 16 f bf16, row stride 32 B
//     WL[s] at 40960+s*8192+4096
//   Epilogue (reuses region): ds[64][264] f32 (67584 B)
__global__ void __launch_bounds__(512, 1)
lnkr_mma_kernel(const float* __restrict__ x, float* __restrict__ out) {
    extern __shared__ char sm[];

    const int t    = threadIdx.x;
    const int lane = t & 31;
    const int w    = t >> 5;
    const int wm   = w >> 2;         // 0..3: 32-g group
    const int wn   = w & 3;          // 0..3: 64-tau group
    const int gc    = blockIdx.x & 3;
    const int ntile = blockIdx.x >> 2;
    const int b     = blockIdx.y;
    const int nbase = ntile * 32;

    // ---- x slab loader decode: thread -> fixed (k, n, f-phase) ----
    const int rr  = t >> 5;          // 0..15
    const int rrh = rr >> 3;         // 0/1 : f sub-row
    const int kk  = rr & 7;          // k
    const float* xbase = x + (size_t)b * FKN + (size_t)rrh * KN_
                           + (size_t)kk * 2048 + nbase + lane;
    const int sts_off = (kk * 32 + lane) * 40 + rrh * 2;   // tau = kk*32+n

    // ---- W slab loader decode ----
    const int whalf = t >> 8;              // 0 = hi, 1 = lo
    const int wrr   = (t & 255) >> 1;      // g row 0..127
    const int wpart = t & 1;               // 16B half of 32B row
    const __nv_bfloat16* wsrc = (whalf ? g_W_lo : g_W_hi)
                              + (size_t)(gc * 128 + wrr) * 512 + wpart * 8;
    const int wsts = whalf * 4096 + wrr * 32 + wpart * 16;

    float acc[2][8][4];
#pragma unroll
    for (int mi = 0; mi < 2; ++mi)
#pragma unroll
        for (int ni = 0; ni < 8; ++ni)
#pragma unroll
            for (int q = 0; q < 4; ++q) acc[mi][ni][q] = 0.0f;

    float v[8];
    uint4 wv;

    // ---- prologue: slab 0 ----
#pragma unroll
    for (int i = 0; i < 8; ++i) v[i] = xbase[i * 32768];
    wv = *(const uint4*)(wsrc);
    {
        char* XH = sm;
        char* XL = sm + 10240;
#pragma unroll
        for (int i = 0; i < 8; ++i) {
            __nv_bfloat16 h = __float2bfloat16(v[i]);
            __nv_bfloat16 l = __float2bfloat16(v[i] - __bfloat162float(h));
            *(__nv_bfloat16*)(XH + sts_off + i * 4) = h;
            *(__nv_bfloat16*)(XL + sts_off + i * 4) = l;
        }
        *(uint4*)(sm + 40960 + wsts) = wv;
    }
    __syncthreads();

    // ---- K loop: 32 slabs of 16 f ----
    for (int c = 0; c < 32; ++c) {
        const int s = c & 1;
        if (c < 31) {
            const float* xp = xbase + (size_t)(c + 1) * 262144;  // +16*KN_
#pragma unroll
            for (int i = 0; i < 8; ++i) v[i] = xp[i * 32768];
            wv = *(const uint4*)(wsrc + (size_t)(c + 1) * 16);
        }
        // compute on stage s
        {
            const char* XH = sm + s * 20480;
            const char* XL = XH + 10240;
            const char* WH = sm + 40960 + s * 8192;
            const char* WL = WH + 4096;

            uint32_t ah[2][4], al[2][4];
#pragma unroll
            for (int mi = 0; mi < 2; ++mi) {
                int rb = (wm * 32 + mi * 16 + (lane >> 2)) * 32 + (lane & 3) * 4;
                ah[mi][0] = *(const uint32_t*)(WH + rb);
                ah[mi][1] = *(const uint32_t*)(WH + rb + 256);
                ah[mi][2] = *(const uint32_t*)(WH + rb + 16);
                ah[mi][3] = *(const uint32_t*)(WH + rb + 272);
                al[mi][0] = *(const uint32_t*)(WL + rb);
                al[mi][1] = *(const uint32_t*)(WL + rb + 256);
                al[mi][2] = *(const uint32_t*)(WL + rb + 16);
                al[mi][3] = *(const uint32_t*)(WL + rb + 272);
            }
#pragma unroll
            for (int ni = 0; ni < 8; ++ni) {
                int tb = (wn * 64 + ni * 8 + (lane >> 2)) * 40 + (lane & 3) * 4;
                uint32_t bh0 = *(const uint32_t*)(XH + tb);
                uint32_t bh1 = *(const uint32_t*)(XH + tb + 16);
                uint32_t bl0 = *(const uint32_t*)(XL + tb);
                uint32_t bl1 = *(const uint32_t*)(XL + tb + 16);
#pragma unroll
                for (int mi = 0; mi < 2; ++mi) {
                    mma16816(acc[mi][ni], ah[mi][0], ah[mi][1], ah[mi][2], ah[mi][3], bh0, bh1);
                    mma16816(acc[mi][ni], al[mi][0], al[mi][1], al[mi][2], al[mi][3], bh0, bh1);
                    mma16816(acc[mi][ni], ah[mi][0], ah[mi][1], ah[mi][2], ah[mi][3], bl0, bl1);
                }
            }
        }
        __syncthreads();
        if (c < 31) {
            const int s1 = (c + 1) & 1;
            char* XH = sm + s1 * 20480;
            char* XL = XH + 10240;
#pragma unroll
            for (int i = 0; i < 8; ++i) {
                __nv_bfloat16 h = __float2bfloat16(v[i]);
                __nv_bfloat16 l = __float2bfloat16(v[i] - __bfloat162float(h));
                *(__nv_bfloat16*)(XH + sts_off + i * 4) = h;
                *(__nv_bfloat16*)(XL + sts_off + i * 4) = l;
            }
            *(uint4*)(sm + 40960 + s1 * 8192 + wsts) = wv;
            __syncthreads();
        }
    }

    // ---- epilogue: two 64-g chunks through smem ----
    float* ds = (float*)sm;           // [64][264] f32
#pragma unroll
    for (int h = 0; h < 2; ++h) {
        if (h) __syncthreads();
        if ((w >> 3) == h) {          // warps wm in {2h, 2h+1} own this chunk
#pragma unroll
            for (int mi = 0; mi < 2; ++mi)
#pragma unroll
                for (int ni = 0; ni < 8; ++ni) {
                    int row  = (wm & 1) * 32 + mi * 16 + (lane >> 2);
                    int tcol = wn * 64 + ni * 8 + (lane & 3) * 2;
                    float* p = ds + row * 264 + tcol;
                    p[0] = acc[mi][ni][0];
                    p[1] = acc[mi][ni][1];
                    p[8 * 264]     = acc[mi][ni][2];
                    p[8 * 264 + 1] = acc[mi][ni][3];
                }
        }
        __syncthreads();
        // consume: 64 g x 32 n items
#pragma unroll
        for (int it = 0; it < 4; ++it) {
            int id  = t + it * 512;
            int g_l = id >> 5, n = id & 31;
            int g   = gc * 128 + h * 64 + g_l;
            size_t base = (size_t)b * FKN + (size_t)g * KN_ + nbase + n;
            float xs[8], dd[8];
#pragma unroll
            for (int k = 0; k < 8; ++k) {
                xs[k] = x[base + (size_t)k * 2048];
                dd[k] = ds[g_l * 264 + k * 32 + n];
            }
            // Killing Gram nonzeros: G00=G44=12, G04=G40=-6, G13=G31=G26=G62=G57=G75=6
            float kf = 6.0f * (2.0f * xs[0] * dd[0] + 2.0f * xs[4] * dd[4]
                               - xs[0] * dd[4] - xs[4] * dd[0]
                               + xs[1] * dd[3] + xs[3] * dd[1]
                               + xs[2] * dd[6] + xs[6] * dd[2]
                               + xs[5] * dd[7] + xs[7] * dd[5]);
            bool pos = (kf > 0.0f);
#pragma unroll
            for (int k = 0; k < 8; ++k)
                out[base + (size_t)k * 2048] = pos ? fmaf(kf, dd[k], xs[k]) : xs[k];
        }
    }
}

extern "C" void kernel_launch(void* const* d_in, const int* in_sizes, int n_in,
                              void* d_out, int out_size)
{
    const float* a0 = (const float*)d_in[0];
    const float* a1 = (const float*)d_in[1];
    const float* x = a0; const float* W = a1;
    if (n_in >= 2 && in_sizes[0] < in_sizes[1]) { x = a1; W = a0; }

    cudaFuncSetAttribute(lnkr_mma_kernel,
                         cudaFuncAttributeMaxDynamicSharedMemorySize, 69632);

    prep_w<<<512, 512>>>(W);
    lnkr_mma_kernel<<<dim3(256, 8), 512, 69632>>>(x, (float*)d_out);
}

// round 6
// speedup vs baseline: 1.8728x; 1.0467x over previous
#include <cuda_runtime.h>
#include <cuda_fp16.h>
#include <cstdint>

#define F_   512
#define KN_  16384       // k*n per (b,f)
#define FKN  8388608     // F_*KN_

// -------- device scratch (allocs forbidden) --------
__device__ __half g_W_hi[512 * 512];
__device__ __half g_W_lo[512 * 512];

// -------- prep: split W into fp16 hi/lo (2-pass Markidis split) --------
__global__ void prep_w(const float* __restrict__ W) {
    int i = blockIdx.x * 512 + threadIdx.x;
    float v = W[i];
    __half h = __float2half(v);
    g_W_hi[i] = h;
    g_W_lo[i] = __float2half(v - __half2float(h));
}

// legacy tensor-core mma, fp16 in / fp32 acc (baseline PTX, plain sm_103 ok)
static __device__ __forceinline__ void mma16816(float* c,
        uint32_t a0, uint32_t a1, uint32_t a2, uint32_t a3,
        uint32_t b0, uint32_t b1) {
    asm volatile(
        "mma.sync.aligned.m16n8k16.row.col.f32.f16.f16.f32 "
        "{%0,%1,%2,%3}, {%4,%5,%6,%7}, {%8,%9}, {%0,%1,%2,%3};"
        : "+f"(c[0]), "+f"(c[1]), "+f"(c[2]), "+f"(c[3])
        : "r"(a0), "r"(a1), "r"(a2), "r"(a3), "r"(b0), "r"(b1));
}

#define SWZ(r) (((r) >> 2) & 7)

// ---------------- fused kernel ----------------
// CTA: 128 g x 256 tau (= 8k x 32n), 512 threads, 16 warps = 4 wm x 4 wn.
// smem: K-loop stage s:
//   X[s]  at s*8192          : 256 rows x 32B (16 fp16 f), XOR-swizzled words
//   WH[s] at 16384 + s*8192  : 128 rows x 32B
//   WL[s] at WH[s] + 4096
// Epilogue reuses region as ds[64][264] f32.
__global__ void __launch_bounds__(512, 1)
lnkr_mma_kernel(const float* __restrict__ x, float* __restrict__ out) {
    extern __shared__ char sm[];

    const int t    = threadIdx.x;
    const int lane = t & 31;
    const int w    = t >> 5;
    const int wm   = w >> 2;         // 0..3: 32-g group
    const int wn   = w & 3;          // 0..3: 64-tau group
    const int lq   = lane >> 2;
    const int lc   = lane & 3;
    const int gc    = blockIdx.x & 3;
    const int ntile = blockIdx.x >> 2;
    const int b     = blockIdx.y;
    const int nbase = ntile * 32;

    // ---- fragment LDS offsets (swizzled, stage-relative) ----
    uint32_t offb[8];
#pragma unroll
    for (int ni = 0; ni < 8; ++ni) {
        int tau = wn * 64 + ni * 8 + lq;
        offb[ni] = tau * 32 + ((lc ^ SWZ(tau)) << 2);
    }
    uint32_t offa[2][2];
#pragma unroll
    for (int mi = 0; mi < 2; ++mi) {
        int r0 = wm * 32 + mi * 16 + lq;
        int r1 = r0 + 8;
        offa[mi][0] = r0 * 32 + ((lc ^ SWZ(r0)) << 2);
        offa[mi][1] = r1 * 32 + ((lc ^ SWZ(r1)) << 2);
    }

    // ---- X loader decode: warp -> (k, f-phase), lane -> n ----
    const int kk = w & 7;
    const int p  = w >> 3;           // f phase: pairs p*4..p*4+3
    const float* xbase = x + (size_t)b * FKN + (size_t)kk * 2048 + nbase + lane;
    const int tau_l = kk * 32 + lane;
    uint32_t stsx[4];
#pragma unroll
    for (int cc = 0; cc < 4; ++cc) {
        int c = p * 4 + cc;
        stsx[cc] = tau_l * 32 + ((c ^ SWZ(tau_l)) << 2);
    }

    // ---- W loader decode ----
    const int whalf = t >> 8;              // 0 = hi, 1 = lo
    const int wrow  = (t & 255) >> 1;      // g row 0..127
    const int wq    = t & 1;               // 8-f half
    const __half* wsrc = (whalf ? g_W_lo : g_W_hi)
                       + (size_t)(gc * 128 + wrow) * 512 + wq * 8;
    uint32_t stsw[4];
#pragma unroll
    for (int cc = 0; cc < 4; ++cc) {
        int c = wq * 4 + cc;
        stsw[cc] = wrow * 32 + ((c ^ SWZ(wrow)) << 2);
    }
    const uint32_t wbase_off = 16384 + whalf * 4096;

    float acc[2][8][4];
#pragma unroll
    for (int mi = 0; mi < 2; ++mi)
#pragma unroll
        for (int ni = 0; ni < 8; ++ni)
#pragma unroll
            for (int q = 0; q < 4; ++q) acc[mi][ni][q] = 0.0f;

    float v[8];
    uint4 wv;

    // ---- prologue: slab 0 ----
    {
        const float* xp = xbase + (size_t)(p * 8) * KN_;
#pragma unroll
        for (int j = 0; j < 8; ++j) v[j] = xp[(size_t)j * KN_];
        wv = *(const uint4*)(wsrc);
        char* Xs = sm;
        uint32_t wd[4] = {wv.x, wv.y, wv.z, wv.w};
#pragma unroll
        for (int cc = 0; cc < 4; ++cc) {
            __half2 hh = __halves2half2(__float2half(v[2 * cc]), __float2half(v[2 * cc + 1]));
            *(uint32_t*)(Xs + stsx[cc]) = *(uint32_t*)&hh;
            *(uint32_t*)(sm + wbase_off + stsw[cc]) = wd[cc];
        }
    }
    __syncthreads();

    // ---- K loop: 32 slabs of 16 f ----
    for (int c = 0; c < 32; ++c) {
        const int s = c & 1;
        if (c < 31) {
            const float* xp = xbase + (size_t)((c + 1) * 16 + p * 8) * KN_;
#pragma unroll
            for (int j = 0; j < 8; ++j) v[j] = xp[(size_t)j * KN_];
            wv = *(const uint4*)(wsrc + (size_t)(c + 1) * 16);
        }
        // compute on stage s
        {
            const char* Xs = sm + s * 8192;
            const char* Wh = sm + 16384 + s * 8192;
            const char* Wl = Wh + 4096;

            uint32_t ah[2][4], al[2][4];
#pragma unroll
            for (int mi = 0; mi < 2; ++mi) {
                ah[mi][0] = *(const uint32_t*)(Wh + offa[mi][0]);
                ah[mi][1] = *(const uint32_t*)(Wh + offa[mi][1]);
                ah[mi][2] = *(const uint32_t*)(Wh + (offa[mi][0] ^ 16));
                ah[mi][3] = *(const uint32_t*)(Wh + (offa[mi][1] ^ 16));
                al[mi][0] = *(const uint32_t*)(Wl + offa[mi][0]);
                al[mi][1] = *(const uint32_t*)(Wl + offa[mi][1]);
                al[mi][2] = *(const uint32_t*)(Wl + (offa[mi][0] ^ 16));
                al[mi][3] = *(const uint32_t*)(Wl + (offa[mi][1] ^ 16));
            }
#pragma unroll
            for (int ni = 0; ni < 8; ++ni) {
                uint32_t b0 = *(const uint32_t*)(Xs + offb[ni]);
                uint32_t b1 = *(const uint32_t*)(Xs + (offb[ni] ^ 16));
#pragma unroll
                for (int mi = 0; mi < 2; ++mi) {
                    mma16816(acc[mi][ni], ah[mi][0], ah[mi][1], ah[mi][2], ah[mi][3], b0, b1);
                    mma16816(acc[mi][ni], al[mi][0], al[mi][1], al[mi][2], al[mi][3], b0, b1);
                }
            }
        }
        __syncthreads();
        if (c < 31) {
            const int s1 = (c + 1) & 1;
            char* Xs = sm + s1 * 8192;
            uint32_t wd[4] = {wv.x, wv.y, wv.z, wv.w};
#pragma unroll
            for (int cc = 0; cc < 4; ++cc) {
                __half2 hh = __halves2half2(__float2half(v[2 * cc]), __float2half(v[2 * cc + 1]));
                *(uint32_t*)(Xs + stsx[cc]) = *(uint32_t*)&hh;
                *(uint32_t*)(sm + wbase_off + s1 * 8192 + stsw[cc]) = wd[cc];
            }
            __syncthreads();
        }
    }

    // ---- epilogue: two 64-g chunks through smem ----
    float* ds = (float*)sm;           // [64][264] f32
#pragma unroll
    for (int h = 0; h < 2; ++h) {
        if (h) __syncthreads();
        if ((w >> 3) == h) {          // warps with wm in {2h, 2h+1} own this chunk
#pragma unroll
            for (int mi = 0; mi < 2; ++mi)
#pragma unroll
                for (int ni = 0; ni < 8; ++ni) {
                    int row  = (wm & 1) * 32 + mi * 16 + lq;
                    int tcol = wn * 64 + ni * 8 + lc * 2;
                    float* pp = ds + row * 264 + tcol;
                    pp[0] = acc[mi][ni][0];
                    pp[1] = acc[mi][ni][1];
                    pp[8 * 264]     = acc[mi][ni][2];
                    pp[8 * 264 + 1] = acc[mi][ni][3];
                }
        }
        __syncthreads();
        // consume: 64 g x 32 n items
#pragma unroll
        for (int it = 0; it < 4; ++it) {
            int id  = t + it * 512;
            int g_l = id >> 5, n = id & 31;
            int g   = gc * 128 + h * 64 + g_l;
            size_t base = (size_t)b * FKN + (size_t)g * KN_ + nbase + n;
            float xs[8], dd[8];
#pragma unroll
            for (int k = 0; k < 8; ++k) {
                xs[k] = x[base + (size_t)k * 2048];
                dd[k] = ds[g_l * 264 + k * 32 + n];
            }
            // Killing Gram nonzeros: G00=G44=12, G04=G40=-6, G13=G31=G26=G62=G57=G75=6
            float kf = 6.0f * (2.0f * xs[0] * dd[0] + 2.0f * xs[4] * dd[4]
                               - xs[0] * dd[4] - xs[4] * dd[0]
                               + xs[1] * dd[3] + xs[3] * dd[1]
                               + xs[2] * dd[6] + xs[6] * dd[2]
                               + xs[5] * dd[7] + xs[7] * dd[5]);
            bool pos = (kf > 0.0f);
#pragma unroll
            for (int k = 0; k < 8; ++k)
                out[base + (size_t)k * 2048] = pos ? fmaf(kf, dd[k], xs[k]) : xs[k];
        }
    }
}

extern "C" void kernel_launch(void* const* d_in, const int* in_sizes, int n_in,
                              void* d_out, int out_size)
{
    const float* a0 = (const float*)d_in[0];
    const float* a1 = (const float*)d_in[1];
    const float* x = a0; const float* W = a1;
    if (n_in >= 2 && in_sizes[0] < in_sizes[1]) { x = a1; W = a0; }

    cudaFuncSetAttribute(lnkr_mma_kernel,
                         cudaFuncAttributeMaxDynamicSharedMemorySize, 67584);

    prep_w<<<512, 512>>>(W);
    lnkr_mma_kernel<<<dim3(256, 8), 512, 67584>>>(x, (float*)d_out);
}

// round 7
// speedup vs baseline: 3.3151x; 1.7701x over previous
#include <cuda_runtime.h>
#include <cuda_fp16.h>
#include <cstdint>

#define F_   512
#define KN_  16384       // k*n per (b,f)
#define FKN  8388608     // F_*KN_

// -------- device scratch (allocs forbidden) --------
__device__ __half g_W_hi[512 * 512];
__device__ __half g_W_lo[512 * 512];
__device__ __half g_xh[(size_t)8 * FKN];   // x in fp16, original layout (128MB)

// -------- prep: split W into fp16 hi/lo (Markidis 2-pass split) --------
__global__ void prep_w(const float* __restrict__ W) {
    int i = blockIdx.x * 512 + threadIdx.x;
    float v = W[i];
    __half h = __float2half(v);
    g_W_hi[i] = h;
    g_W_lo[i] = __float2half(v - __half2float(h));
}

// -------- prep: x -> fp16, same layout --------
__global__ void __launch_bounds__(256) prep_xh(const float* __restrict__ x) {
    size_t i = (size_t)blockIdx.x * 256 + threadIdx.x;   // *4 elements
    float4 v = ((const float4*)x)[i];
    __half2 h0 = __floats2half2_rn(v.x, v.y);
    __half2 h1 = __floats2half2_rn(v.z, v.w);
    uint2 u;
    u.x = *(uint32_t*)&h0;
    u.y = *(uint32_t*)&h1;
    ((uint2*)g_xh)[i] = u;
}

// -------- PTX helpers (all baseline PTX, plain sm_103 target OK) --------
static __device__ __forceinline__ uint32_t smem_u32(const void* p) {
    uint32_t a;
    asm("{ .reg .u64 t; cvta.to.shared.u64 t, %1; cvt.u32.u64 %0, t; }" : "=r"(a) : "l"(p));
    return a;
}
static __device__ __forceinline__ void cpa16(uint32_t dst, const void* src) {
    asm volatile("cp.async.cg.shared.global [%0], [%1], 16;"
                 :: "r"(dst), "l"(__cvta_generic_to_global(src)));
}
static __device__ __forceinline__ void cp_commit() {
    asm volatile("cp.async.commit_group;" ::: "memory");
}
template <int NN> static __device__ __forceinline__ void cp_wait() {
    asm volatile("cp.async.wait_group %0;" :: "n"(NN) : "memory");
}
static __device__ __forceinline__ void ldsm4(uint32_t* r, uint32_t a) {
    asm volatile("ldmatrix.sync.aligned.m8n8.x4.shared.b16 {%0,%1,%2,%3}, [%4];"
                 : "=r"(r[0]), "=r"(r[1]), "=r"(r[2]), "=r"(r[3]) : "r"(a));
}
static __device__ __forceinline__ void ldsm4t(uint32_t* r, uint32_t a) {
    asm volatile("ldmatrix.sync.aligned.m8n8.x4.trans.shared.b16 {%0,%1,%2,%3}, [%4];"
                 : "=r"(r[0]), "=r"(r[1]), "=r"(r[2]), "=r"(r[3]) : "r"(a));
}
static __device__ __forceinline__ void mma16816(float* c,
        uint32_t a0, uint32_t a1, uint32_t a2, uint32_t a3,
        uint32_t b0, uint32_t b1) {
    asm volatile(
        "mma.sync.aligned.m16n8k16.row.col.f32.f16.f16.f32 "
        "{%0,%1,%2,%3}, {%4,%5,%6,%7}, {%8,%9}, {%0,%1,%2,%3};"
        : "+f"(c[0]), "+f"(c[1]), "+f"(c[2]), "+f"(c[3])
        : "r"(a0), "r"(a1), "r"(a2), "r"(a3), "r"(b0), "r"(b1));
}

// ---------------- fused kernel ----------------
// CTA: 128 g x 256 tau (= 8k x 32n). 512 threads, 16 warps = 4 wm x 4 wn.
// smem: 4 stages of 16KB:
//   X at s*16384        : 16 f-rows x 512B (256 tau fp16), 16B-chunk XOR swizzle
//   Wh at s*16384+8192  : 128 g-rows x 32B (16 f fp16), chunk swizzled by (g>>2)&1
//   Wl at Wh + 4096
// Epilogue reuses region as ds[64][264] f32 (67584 B).
__global__ void __launch_bounds__(512, 1)
lnkr_mma_kernel(const float* __restrict__ x, float* __restrict__ out) {
    extern __shared__ char sm_[];
    const uint32_t smb = smem_u32(sm_);

    const int t    = threadIdx.x;
    const int lane = t & 31;
    const int w    = t >> 5;
    const int wm   = w >> 2;         // 0..3: 32-g group
    const int wn   = w & 3;          // 0..3: 64-tau group
    const int lq   = lane >> 2;
    const int lc   = lane & 3;
    const int lr   = lane & 7;
    const int grp  = lane >> 3;
    const int gc    = blockIdx.x & 3;
    const int ntile = blockIdx.x >> 2;
    const int b     = blockIdx.y;
    const int nbase = ntile * 32;

    // ---- cp.async decode: each thread moves one 16B X granule + one 16B W granule ----
    const int fr = t >> 5;                 // f row 0..15
    const int kk = (t >> 2) & 7;           // k
    const int gp = t & 3;                  // 16B part within 64B n-chunk
    const __half* xsrc0 = g_xh + (size_t)b * FKN + (size_t)fr * KN_
                               + kk * 2048 + nbase + gp * 8;
    const uint32_t xdst = fr * 512 + (((kk * 4 + gp) ^ (fr & 7)) << 4);

    const int whalf = t >> 8;              // 0 = hi, 1 = lo
    const int wgr   = (t & 255) >> 1;      // g row 0..127
    const int wpart = t & 1;
    const __half* wsrc0 = (whalf ? g_W_lo : g_W_hi)
                        + (size_t)(gc * 128 + wgr) * 512 + wpart * 8;
    const uint32_t wdst = 8192 + whalf * 4096 + wgr * 32
                        + ((wpart ^ ((wgr >> 2) & 1)) << 4);

    // ---- ldmatrix offsets (stage-relative) ----
    // B (trans): matrix q covers (ni = 2q + grp>>1, kh = grp&1)
    uint32_t offB[4];
#pragma unroll
    for (int q = 0; q < 4; ++q) {
        int f    = (grp & 1) * 8 + lr;
        int tau0 = wn * 64 + (2 * q + (grp >> 1)) * 8;
        offB[q] = f * 512 + ((((tau0 >> 3) ^ (f & 7))) << 4);
    }
    // A (non-trans): groups = (rows +0/+8) x (f-chunk 0/1)
    uint32_t offAh[2], offAl[2];
#pragma unroll
    for (int mi = 0; mi < 2; ++mi) {
        int g  = wm * 32 + mi * 16 + (grp & 1) * 8 + lr;
        int ch = (grp >> 1) ^ ((g >> 2) & 1);
        offAh[mi] = 8192 + g * 32 + (ch << 4);
        offAl[mi] = offAh[mi] + 4096;
    }

    float acc[2][8][4];
#pragma unroll
    for (int mi = 0; mi < 2; ++mi)
#pragma unroll
        for (int ni = 0; ni < 8; ++ni)
#pragma unroll
            for (int q = 0; q < 4; ++q) acc[mi][ni][q] = 0.0f;

    // ---- prologue: 3 stages in flight ----
#pragma unroll
    for (int s = 0; s < 3; ++s) {
        uint32_t base = smb + s * 16384;
        cpa16(base + xdst, xsrc0 + (size_t)s * 16 * KN_);
        cpa16(base + wdst, wsrc0 + s * 16);
        cp_commit();
    }

    // ---- K loop: 32 slabs of 16 f, single sync per slab ----
    for (int c = 0; c < 32; ++c) {
        cp_wait<2>();
        __syncthreads();
        const uint32_t base = smb + (c & 3) * 16384;

        uint32_t Ah[2][4], Al[2][4], Bx[4][4];
        ldsm4(Ah[0], base + offAh[0]);
        ldsm4(Ah[1], base + offAh[1]);
        ldsm4(Al[0], base + offAl[0]);
        ldsm4(Al[1], base + offAl[1]);
#pragma unroll
        for (int q = 0; q < 4; ++q) ldsm4t(Bx[q], base + offB[q]);

#pragma unroll
        for (int q = 0; q < 4; ++q) {
#pragma unroll
            for (int j = 0; j < 2; ++j) {
                uint32_t b0 = Bx[q][2 * j], b1 = Bx[q][2 * j + 1];
                int ni = 2 * q + j;
#pragma unroll
                for (int mi = 0; mi < 2; ++mi) {
                    mma16816(acc[mi][ni], Ah[mi][0], Ah[mi][1], Ah[mi][2], Ah[mi][3], b0, b1);
                    mma16816(acc[mi][ni], Al[mi][0], Al[mi][1], Al[mi][2], Al[mi][3], b0, b1);
                }
            }
        }

        if (c + 3 < 32) {
            uint32_t nb = smb + ((c + 3) & 3) * 16384;
            cpa16(nb + xdst, xsrc0 + (size_t)(c + 3) * 16 * KN_);
            cpa16(nb + wdst, wsrc0 + (c + 3) * 16);
        }
        cp_commit();   // always commit -> uniform wait_group<2>
    }
    __syncthreads();

    // ---- epilogue: two 64-g chunks through smem (identical to validated R6) ----
    float* ds = (float*)sm_;          // [64][264] f32
#pragma unroll
    for (int h = 0; h < 2; ++h) {
        if (h) __syncthreads();
        if ((w >> 3) == h) {          // warps with wm in {2h, 2h+1} own this chunk
#pragma unroll
            for (int mi = 0; mi < 2; ++mi)
#pragma unroll
                for (int ni = 0; ni < 8; ++ni) {
                    int row  = (wm & 1) * 32 + mi * 16 + lq;
                    int tcol = wn * 64 + ni * 8 + lc * 2;
                    float* pp = ds + row * 264 + tcol;
                    pp[0] = acc[mi][ni][0];
                    pp[1] = acc[mi][ni][1];
                    pp[8 * 264]     = acc[mi][ni][2];
                    pp[8 * 264 + 1] = acc[mi][ni][3];
                }
        }
        __syncthreads();
        // consume: 64 g x 32 n items
#pragma unroll
        for (int it = 0; it < 4; ++it) {
            int id  = t + it * 512;
            int g_l = id >> 5, n = id & 31;
            int g   = gc * 128 + h * 64 + g_l;
            size_t base = (size_t)b * FKN + (size_t)g * KN_ + nbase + n;
            float xs[8], dd[8];
#pragma unroll
            for (int k = 0; k < 8; ++k) {
                xs[k] = x[base + (size_t)k * 2048];
                dd[k] = ds[g_l * 264 + k * 32 + n];
            }
            // Killing Gram nonzeros: G00=G44=12, G04=G40=-6, G13=G31=G26=G62=G57=G75=6
            float kf = 6.0f * (2.0f * xs[0] * dd[0] + 2.0f * xs[4] * dd[4]
                               - xs[0] * dd[4] - xs[4] * dd[0]
                               + xs[1] * dd[3] + xs[3] * dd[1]
                               + xs[2] * dd[6] + xs[6] * dd[2]
                               + xs[5] * dd[7] + xs[7] * dd[5]);
            bool pos = (kf > 0.0f);
#pragma unroll
            for (int k = 0; k < 8; ++k)
                out[base + (size_t)k * 2048] = pos ? fmaf(kf, dd[k], xs[k]) : xs[k];
        }
    }
}

extern "C" void kernel_launch(void* const* d_in, const int* in_sizes, int n_in,
                              void* d_out, int out_size)
{
    const float* a0 = (const float*)d_in[0];
    const float* a1 = (const float*)d_in[1];
    const float* x = a0; const float* W = a1;
    if (n_in >= 2 && in_sizes[0] < in_sizes[1]) { x = a1; W = a0; }

    cudaFuncSetAttribute(lnkr_mma_kernel,
                         cudaFuncAttributeMaxDynamicSharedMemorySize, 67584);

    prep_w<<<512, 512>>>(W);
    prep_xh<<<65536, 256>>>(x);
    lnkr_mma_kernel<<<dim3(256, 8), 512, 67584>>>(x, (float*)d_out);
}

// round 8
// speedup vs baseline: 4.0783x; 1.2302x over previous
#include <cuda_runtime.h>
#include <cuda_fp16.h>
#include <cstdint>

#define F_   512
#define KN_  16384       // k*n per (b,f)
#define FKN  8388608     // F_*KN_

// -------- device scratch (allocs forbidden) --------
__device__ __half g_W[512 * 512];          // W fp16
__device__ __half g_xh[(size_t)8 * FKN];   // x fp16, original layout (128MB)

// -------- prep: W -> fp16 --------
__global__ void prep_w(const float* __restrict__ W) {
    int i = blockIdx.x * 512 + threadIdx.x;
    g_W[i] = __float2half(W[i]);
}

// -------- prep: x -> fp16, same layout --------
__global__ void __launch_bounds__(256) prep_xh(const float* __restrict__ x) {
    size_t i = (size_t)blockIdx.x * 256 + threadIdx.x;   // *4 elements
    float4 v = ((const float4*)x)[i];
    __half2 h0 = __floats2half2_rn(v.x, v.y);
    __half2 h1 = __floats2half2_rn(v.z, v.w);
    uint2 u;
    u.x = *(uint32_t*)&h0;
    u.y = *(uint32_t*)&h1;
    ((uint2*)g_xh)[i] = u;
}

// -------- PTX helpers (baseline PTX, plain sm_103 target OK) --------
static __device__ __forceinline__ uint32_t smem_u32(const void* p) {
    uint32_t a;
    asm("{ .reg .u64 t; cvta.to.shared.u64 t, %1; cvt.u32.u64 %0, t; }" : "=r"(a) : "l"(p));
    return a;
}
static __device__ __forceinline__ void cpa16(uint32_t dst, const void* src) {
    asm volatile("cp.async.cg.shared.global [%0], [%1], 16;"
                 :: "r"(dst), "l"(__cvta_generic_to_global(src)));
}
static __device__ __forceinline__ void cp_commit() {
    asm volatile("cp.async.commit_group;" ::: "memory");
}
template <int NN> static __device__ __forceinline__ void cp_wait() {
    asm volatile("cp.async.wait_group %0;" :: "n"(NN) : "memory");
}
static __device__ __forceinline__ void ldsm4(uint32_t* r, uint32_t a) {
    asm volatile("ldmatrix.sync.aligned.m8n8.x4.shared.b16 {%0,%1,%2,%3}, [%4];"
                 : "=r"(r[0]), "=r"(r[1]), "=r"(r[2]), "=r"(r[3]) : "r"(a));
}
static __device__ __forceinline__ void ldsm4t(uint32_t* r, uint32_t a) {
    asm volatile("ldmatrix.sync.aligned.m8n8.x4.trans.shared.b16 {%0,%1,%2,%3}, [%4];"
                 : "=r"(r[0]), "=r"(r[1]), "=r"(r[2]), "=r"(r[3]) : "r"(a));
}
static __device__ __forceinline__ void mma16816(float* c,
        uint32_t a0, uint32_t a1, uint32_t a2, uint32_t a3,
        uint32_t b0, uint32_t b1) {
    asm volatile(
        "mma.sync.aligned.m16n8k16.row.col.f32.f16.f16.f32 "
        "{%0,%1,%2,%3}, {%4,%5,%6,%7}, {%8,%9}, {%0,%1,%2,%3};"
        : "+f"(c[0]), "+f"(c[1]), "+f"(c[2]), "+f"(c[3])
        : "r"(a0), "r"(a1), "r"(a2), "r"(a3), "r"(b0), "r"(b1));
}

// ---------------- fused kernel ----------------
// CTA: 128 g x 256 tau (= 8k x 32n). 512 threads, 16 warps = 4 wm x 4 wn.
// smem: 4 stages of 12KB:
//   X at s*12288        : 16 f-rows x 512B (256 tau fp16), 16B-chunk XOR swizzle
//   W at s*12288+8192   : 128 g-rows x 32B (16 f fp16), chunk swizzled by (g>>2)&1
// Epilogue reuses region as ds[64][264] f32 (67584 B).
__global__ void __launch_bounds__(512, 1)
lnkr_mma_kernel(const float* __restrict__ x, float* __restrict__ out) {
    extern __shared__ char sm_[];
    const uint32_t smb = smem_u32(sm_);

    const int t    = threadIdx.x;
    const int lane = t & 31;
    const int w    = t >> 5;
    const int wm   = w >> 2;         // 0..3: 32-g group
    const int wn   = w & 3;          // 0..3: 64-tau group
    const int lq   = lane >> 2;
    const int lc   = lane & 3;
    const int lr   = lane & 7;
    const int grp  = lane >> 3;
    const int gc    = blockIdx.x & 3;
    const int ntile = blockIdx.x >> 2;
    const int b     = blockIdx.y;
    const int nbase = ntile * 32;

    // ---- cp.async decode ----
    // X: every thread moves one 16B granule per slab
    const int fr = t >> 5;                 // f row 0..15
    const int kk = (t >> 2) & 7;           // k
    const int gp = t & 3;                  // 16B part within 64B n-chunk
    const __half* xsrc0 = g_xh + (size_t)b * FKN + (size_t)fr * KN_
                               + kk * 2048 + nbase + gp * 8;
    const uint32_t xdst = fr * 512 + (((kk * 4 + gp) ^ (fr & 7)) << 4);

    // W: threads t<256 move one 16B granule per slab
    const bool wload = (t < 256);
    const int wgr   = t >> 1;              // g row 0..127
    const int wpart = t & 1;
    const __half* wsrc0 = g_W + (size_t)(gc * 128 + (wgr & 127)) * 512 + wpart * 8;
    const uint32_t wdst = 8192 + (wgr & 127) * 32
                        + ((wpart ^ ((wgr >> 2) & 1)) << 4);

    // ---- ldmatrix offsets (stage-relative) ----
    // B (trans): matrix q covers (ni = 2q + grp>>1, kh = grp&1)
    uint32_t offB[4];
#pragma unroll
    for (int q = 0; q < 4; ++q) {
        int f    = (grp & 1) * 8 + lr;
        int tau0 = wn * 64 + (2 * q + (grp >> 1)) * 8;
        offB[q] = f * 512 + ((((tau0 >> 3) ^ (f & 7))) << 4);
    }
    // A (non-trans): groups = (rows +0/+8) x (f-chunk 0/1)
    uint32_t offA[2];
#pragma unroll
    for (int mi = 0; mi < 2; ++mi) {
        int g  = wm * 32 + mi * 16 + (grp & 1) * 8 + lr;
        int ch = (grp >> 1) ^ ((g >> 2) & 1);
        offA[mi] = 8192 + g * 32 + (ch << 4);
    }

    float acc[2][8][4];
#pragma unroll
    for (int mi = 0; mi < 2; ++mi)
#pragma unroll
        for (int ni = 0; ni < 8; ++ni)
#pragma unroll
            for (int q = 0; q < 4; ++q) acc[mi][ni][q] = 0.0f;

    // ---- prologue: 3 stages in flight ----
#pragma unroll
    for (int s = 0; s < 3; ++s) {
        uint32_t base = smb + s * 12288;
        cpa16(base + xdst, xsrc0 + (size_t)s * 16 * KN_);
        if (wload) cpa16(base + wdst, wsrc0 + s * 16);
        cp_commit();
    }

    // ---- K loop: 32 slabs of 16 f, single sync per slab ----
    for (int c = 0; c < 32; ++c) {
        cp_wait<2>();
        __syncthreads();
        const uint32_t base = smb + (c & 3) * 12288;

        uint32_t A[2][4], Bx[4][4];
        ldsm4(A[0], base + offA[0]);
        ldsm4(A[1], base + offA[1]);
#pragma unroll
        for (int q = 0; q < 4; ++q) ldsm4t(Bx[q], base + offB[q]);

#pragma unroll
        for (int q = 0; q < 4; ++q) {
#pragma unroll
            for (int j = 0; j < 2; ++j) {
                uint32_t b0 = Bx[q][2 * j], b1 = Bx[q][2 * j + 1];
                int ni = 2 * q + j;
#pragma unroll
                for (int mi = 0; mi < 2; ++mi)
                    mma16816(acc[mi][ni], A[mi][0], A[mi][1], A[mi][2], A[mi][3], b0, b1);
            }
        }

        if (c + 3 < 32) {
            uint32_t nb = smb + ((c + 3) & 3) * 12288;
            cpa16(nb + xdst, xsrc0 + (size_t)(c + 3) * 16 * KN_);
            if (wload) cpa16(nb + wdst, wsrc0 + (c + 3) * 16);
        }
        cp_commit();   // uniform -> wait_group<2> stays valid
    }
    __syncthreads();

    // ---- epilogue: two 64-g chunks through smem (validated R6/R7) ----
    float* ds = (float*)sm_;          // [64][264] f32
#pragma unroll
    for (int h = 0; h < 2; ++h) {
        if (h) __syncthreads();
        if ((w >> 3) == h) {          // warps with wm in {2h, 2h+1} own this chunk
#pragma unroll
            for (int mi = 0; mi < 2; ++mi)
#pragma unroll
                for (int ni = 0; ni < 8; ++ni) {
                    int row  = (wm & 1) * 32 + mi * 16 + lq;
                    int tcol = wn * 64 + ni * 8 + lc * 2;
                    float* pp = ds + row * 264 + tcol;
                    pp[0] = acc[mi][ni][0];
                    pp[1] = acc[mi][ni][1];
                    pp[8 * 264]     = acc[mi][ni][2];
                    pp[8 * 264 + 1] = acc[mi][ni][3];
                }
        }
        __syncthreads();
        // consume: 64 g x 32 n items
#pragma unroll
        for (int it = 0; it < 4; ++it) {
            int id  = t + it * 512;
            int g_l = id >> 5, n = id & 31;
            int g   = gc * 128 + h * 64 + g_l;
            size_t base = (size_t)b * FKN + (size_t)g * KN_ + nbase + n;
            float xs[8], dd[8];
#pragma unroll
            for (int k = 0; k < 8; ++k) {
                xs[k] = x[base + (size_t)k * 2048];
                dd[k] = ds[g_l * 264 + k * 32 + n];
            }
            // Killing Gram nonzeros: G00=G44=12, G04=G40=-6, G13=G31=G26=G62=G57=G75=6
            float kf = 6.0f * (2.0f * xs[0] * dd[0] + 2.0f * xs[4] * dd[4]
                               - xs[0] * dd[4] - xs[4] * dd[0]
                               + xs[1] * dd[3] + xs[3] * dd[1]
                               + xs[2] * dd[6] + xs[6] * dd[2]
                               + xs[5] * dd[7] + xs[7] * dd[5]);
            bool pos = (kf > 0.0f);
#pragma unroll
            for (int k = 0; k < 8; ++k)
                out[base + (size_t)k * 2048] = pos ? fmaf(kf, dd[k], xs[k]) : xs[k];
        }
    }
}

extern "C" void kernel_launch(void* const* d_in, const int* in_sizes, int n_in,
                              void* d_out, int out_size)
{
    const float* a0 = (const float*)d_in[0];
    const float* a1 = (const float*)d_in[1];
    const float* x = a0; const float* W = a1;
    if (n_in >= 2 && in_sizes[0] < in_sizes[1]) { x = a1; W = a0; }

    cudaFuncSetAttribute(lnkr_mma_kernel,
                         cudaFuncAttributeMaxDynamicSharedMemorySize, 67584);

    prep_w<<<512, 512>>>(W);
    prep_xh<<<65536, 256>>>(x);
    lnkr_mma_kernel<<<dim3(256, 8), 512, 67584>>>(x, (float*)d_out);
}